// round 2
// baseline (speedup 1.0000x reference)
#include <cuda_runtime.h>
#include <math.h>

#define BB 4
#define TT 192
#define LL 120
#define GG 500
#define HH 500      // HL
#define H4 2000
#define NR 480      // B*L
#define OD 24
#define M1 3000
#define M2 1000

// ------------------------- scratch (device globals) -------------------------
__device__ float g_P[GG];
__device__ float g_Nv[GG];
__device__ float g_rho[GG];     // sorted breakpoints
__device__ float g_esign[GG];
__device__ int   g_ef[GG];
__device__ int   g_act0[GG];
__device__ int   g_nev[1];
__device__ float g_bias[H4];
__device__ float g_Aseg[(GG + 1) * H4];
__device__ float g_Bseg[(GG + 1) * H4];
__device__ float g_WihT[GG * H4];   // [f][h]
__device__ float g_WX[HH * H4];     // [k][hc*4+gate]
__device__ float g_u[TT * NR];
__device__ float g_v[TT * NR];
__device__ int   g_seg[TT * NR];
__device__ float g_hA[HH * NR];     // h, k-major: [hcol][n]
__device__ float g_hB[HH * NR];
__device__ float g_c[HH * NR];      // c, k-major
__device__ float g_hT[NR * HH];     // h_last row-major for MLP
__device__ float g_z1[NR * M1];
__device__ float g_z2[NR * M2];
__device__ float g_z3[NR * M1];

// ------------------------- math helpers -------------------------
__device__ __forceinline__ float fsig(float x) {
    return __fdividef(1.f, 1.f + __expf(-x));
}
__device__ __forceinline__ float ftanh(float x) {
    float ax = fabsf(x);
    float t  = __expf(-2.f * ax);
    float r  = __fdividef(1.f - t, 1.f + t);
    return copysignf(r, x);
}

// ------------------------- P,N precompute -------------------------
// P_f = sum_g relu(W1_g) W2[g,f];  N_f = sum_g relu(-W1_g) W2[g,f]
__global__ void k_prep_pn(const float* __restrict__ W1, const float* __restrict__ W2) {
    int f = threadIdx.x;
    if (f >= GG) return;
    float p = 0.f, n = 0.f;
    for (int g = 0; g < GG; g++) {
        float w = W1[g];
        float v = W2[g * GG + f];
        p = fmaf(fmaxf(w, 0.f), v, p);
        n = fmaf(fmaxf(-w, 0.f), v, n);
    }
    g_P[f]  = p;
    g_Nv[f] = n;
}

// ------------------------- relu breakpoint events + sort -------------------------
__global__ void k_events() {
    __shared__ float srho[GG];
    __shared__ float ssg[GG];
    __shared__ int   sf[GG];
    __shared__ int   cnt;
    int tid = threadIdx.x;
    if (tid == 0) cnt = 0;
    __syncthreads();
    if (tid < GG) {
        float p = g_P[tid], n = g_Nv[tid];
        int act0 = 0;
        float sgn = 0.f, rho = 0.f;
        if (n > 0.f) {
            if (p >= 0.f) { act0 = 1; }
            else { act0 = 0; rho = __fdividef(-p, n); sgn = 1.f; }
        } else if (n < 0.f) {
            if (p > 0.f) { act0 = 1; rho = __fdividef(p, -n); sgn = -1.f; }
            else { act0 = 0; }
        } else {
            act0 = (p > 0.f) ? 1 : 0;
        }
        g_act0[tid] = act0;
        if (sgn != 0.f) {
            int e = atomicAdd(&cnt, 1);
            srho[e] = rho; ssg[e] = sgn; sf[e] = tid;
        }
    }
    __syncthreads();
    int E = cnt;
    if (tid == 0) g_nev[0] = E;
    if (tid < E) {
        float r = srho[tid];
        int rank = 0;
        for (int j = 0; j < E; j++) {
            float rj = srho[j];
            rank += (rj < r) || (rj == r && j < tid);
        }
        g_rho[rank]   = r;
        g_esign[rank] = ssg[tid];
        g_ef[rank]    = sf[tid];
    }
}

// ------------------------- transposes / interleave -------------------------
__global__ void k_wihT(const float* __restrict__ W_ih) {
    int idx = blockIdx.x * 256 + threadIdx.x;
    if (idx >= GG * H4) return;
    int f = idx / H4, h = idx % H4;
    g_WihT[idx] = W_ih[h * GG + f];  // writes coalesced
}

__global__ void k_wx(const float* __restrict__ W_hh,
                     const float* __restrict__ b_ih, const float* __restrict__ b_hh) {
    int idx = blockIdx.x * 256 + threadIdx.x;
    if (idx < H4) g_bias[idx] = b_ih[idx] + b_hh[idx];
    if (idx >= HH * H4) return;
    int k = idx / H4, q = idx % H4;
    int hc = q >> 2, g = q & 3;
    g_WX[idx] = W_hh[(g * HH + hc) * HH + k];  // writes coalesced
}

// ------------------------- segment prefix tables -------------------------
__global__ void k_tables() {
    int h = blockIdx.x * 256 + threadIdx.x;
    if (h >= H4) return;
    float accA = 0.f, accB = 0.f;
    for (int f = 0; f < GG; f++) {
        if (g_act0[f]) {
            float w = g_WihT[f * H4 + h];
            accA = fmaf(w, g_P[f],  accA);
            accB = fmaf(w, g_Nv[f], accB);
        }
    }
    g_Aseg[h] = accA;
    g_Bseg[h] = accB;
    int E = g_nev[0];
    for (int e = 0; e < E; e++) {
        int f = g_ef[e];
        float sgn = g_esign[e];
        float w = g_WihT[f * H4 + h] * sgn;
        accA = fmaf(w, g_P[f],  accA);
        accB = fmaf(w, g_Nv[f], accB);
        g_Aseg[(e + 1) * H4 + h] = accA;
        g_Bseg[(e + 1) * H4 + h] = accB;
    }
}

// ------------------------- GCN front: s, u, v per (b,t) -------------------------
__global__ void k_front(const float* __restrict__ x, const float* __restrict__ Ahat) {
    __shared__ float xr[LL], sp[LL], sn[LL];
    int bid = blockIdx.x;           // b*TT + t
    int b = bid / TT, t = bid % TT;
    int tid = threadIdx.x;
    if (tid < LL) xr[tid] = x[(b * TT + t) * LL + tid];
    __syncthreads();
    if (tid < LL) {
        float s = 0.f;
        const float* Ar = &Ahat[tid * LL];
        for (int l = 0; l < LL; l++) s = fmaf(Ar[l], xr[l], s);
        sp[tid] = fmaxf(s, 0.f);
        sn[tid] = fmaxf(-s, 0.f);
    }
    __syncthreads();
    if (tid < LL) {
        float uu = 0.f, vv = 0.f;
        const float* Ar = &Ahat[tid * LL];
        for (int l = 0; l < LL; l++) {
            uu = fmaf(Ar[l], sp[l], uu);
            vv = fmaf(Ar[l], sn[l], vv);
        }
        int n = b * LL + tid;
        g_u[t * NR + n] = uu;
        g_v[t * NR + n] = vv;
    }
}

// ------------------------- segment lookup per point -------------------------
__global__ void k_seg() {
    int idx = blockIdx.x * 256 + threadIdx.x;
    if (idx >= TT * NR) return;
    float uu = g_u[idx], vv = g_v[idx];
    int E = g_nev[0];
    int s;
    if (uu > 0.f) {
        float rho = vv / uu;
        int lo = 0, hi = E;
        while (lo < hi) {
            int mid = (lo + hi) >> 1;
            if (g_rho[mid] < rho) lo = mid + 1; else hi = mid;
        }
        s = lo;
    } else {
        s = (vv > 0.f) ? E : 0;
    }
    g_seg[idx] = s;
}

// ------------------------- init h,c -------------------------
__global__ void k_init() {
    int idx = blockIdx.x * 256 + threadIdx.x;
    if (idx < HH * NR) g_hA[idx] = 0.f;
    else if (idx < 2 * HH * NR) g_c[idx - HH * NR] = 0.f;
}

// ------------------------- fused LSTM step -------------------------
// block: 32 h-cols (x) x 32 rows (y); thread (ty,tx): 4 rows x 1 hcol x 4 gates
__global__ __launch_bounds__(256) void k_step(int t, int parity) {
    const float* hin = parity ? g_hB : g_hA;
    float*      hout = parity ? g_hA : g_hB;
    __shared__ __align__(16) float Ws[25][128];
    __shared__ __align__(16) float hs[25][32];
    int tid = threadIdx.x;
    int tx = tid & 31;     // hcol local
    int ty = tid >> 5;     // row group 0..7
    int hc0 = blockIdx.x * 32;
    int n0  = blockIdx.y * 32;
    int hc = hc0 + tx;
    int nbase = n0 + ty * 4;
    bool valid = (hc < HH);

    float acc[4][4];
    if (valid) {
        #pragma unroll
        for (int r = 0; r < 4; r++) {
            int pidx = t * NR + nbase + r;
            float uu = g_u[pidx], vv = g_v[pidx];
            int s = g_seg[pidx];
            const float* Ar = &g_Aseg[s * H4];
            const float* Br = &g_Bseg[s * H4];
            #pragma unroll
            for (int g = 0; g < 4; g++) {
                int gc = g * HH + hc;
                acc[r][g] = fmaf(uu, Ar[gc], fmaf(vv, Br[gc], g_bias[gc]));
            }
        }
    } else {
        #pragma unroll
        for (int r = 0; r < 4; r++)
            #pragma unroll
            for (int g = 0; g < 4; g++) acc[r][g] = 0.f;
    }

    for (int k0 = 0; k0 < HH; k0 += 25) {
        for (int e = tid; e < 25 * 128; e += 256) {
            int kk = e >> 7, j = e & 127;
            int col = hc0 * 4 + j;
            Ws[kk][j] = (col < H4) ? g_WX[(k0 + kk) * H4 + col] : 0.f;
        }
        for (int e = tid; e < 25 * 32; e += 256) {
            int kk = e >> 5, nn = e & 31;
            hs[kk][nn] = hin[(k0 + kk) * NR + n0 + nn];
        }
        __syncthreads();
        #pragma unroll
        for (int kk = 0; kk < 25; kk++) {
            float4 hv = *(const float4*)&hs[kk][ty * 4];
            float4 wv = *(const float4*)&Ws[kk][tx * 4];
            acc[0][0] = fmaf(hv.x, wv.x, acc[0][0]);
            acc[0][1] = fmaf(hv.x, wv.y, acc[0][1]);
            acc[0][2] = fmaf(hv.x, wv.z, acc[0][2]);
            acc[0][3] = fmaf(hv.x, wv.w, acc[0][3]);
            acc[1][0] = fmaf(hv.y, wv.x, acc[1][0]);
            acc[1][1] = fmaf(hv.y, wv.y, acc[1][1]);
            acc[1][2] = fmaf(hv.y, wv.z, acc[1][2]);
            acc[1][3] = fmaf(hv.y, wv.w, acc[1][3]);
            acc[2][0] = fmaf(hv.z, wv.x, acc[2][0]);
            acc[2][1] = fmaf(hv.z, wv.y, acc[2][1]);
            acc[2][2] = fmaf(hv.z, wv.z, acc[2][2]);
            acc[2][3] = fmaf(hv.z, wv.w, acc[2][3]);
            acc[3][0] = fmaf(hv.w, wv.x, acc[3][0]);
            acc[3][1] = fmaf(hv.w, wv.y, acc[3][1]);
            acc[3][2] = fmaf(hv.w, wv.z, acc[3][2]);
            acc[3][3] = fmaf(hv.w, wv.w, acc[3][3]);
        }
        __syncthreads();
    }

    if (valid) {
        int cb = hc * NR + nbase;
        float4 cold = *(float4*)&g_c[cb];
        float cv[4] = {cold.x, cold.y, cold.z, cold.w};
        float hv[4];
        #pragma unroll
        for (int r = 0; r < 4; r++) {
            float ig = fsig(acc[r][0]);
            float fg = fsig(acc[r][1]);
            float gg = ftanh(acc[r][2]);
            float og = fsig(acc[r][3]);
            float cn = fmaf(fg, cv[r], ig * gg);
            cv[r] = cn;
            hv[r] = og * ftanh(cn);
        }
        *(float4*)&g_c[cb]  = make_float4(cv[0], cv[1], cv[2], cv[3]);
        *(float4*)&hout[cb] = make_float4(hv[0], hv[1], hv[2], hv[3]);
    }
}

// ------------------------- transpose h_last to row-major -------------------------
__global__ void k_trh() {
    int idx = blockIdx.x * 256 + threadIdx.x;
    if (idx >= NR * HH) return;
    int n = idx / HH, k = idx % HH;
    g_hT[idx] = g_hA[k * NR + n];   // t=191 (odd) wrote into g_hA
}

// ------------------------- generic tiled GEMM: C = act(A @ W + b) -------------------------
__device__ __forceinline__ float* selbuf(int s) {
    switch (s) {
        case 0: return g_hT;
        case 1: return g_z1;
        case 2: return g_z2;
        default: return g_z3;
    }
}

__global__ __launch_bounds__(256) void k_gemm(int aSel, const float* __restrict__ W,
                                              const float* __restrict__ bias, int cSel,
                                              int M, int K, int Nn, int doRelu) {
    const float* A = selbuf(aSel);
    float* C = selbuf(cSel);
    __shared__ __align__(16) float As[16][68];
    __shared__ __align__(16) float Wsm[16][64];
    int tid = threadIdx.x;
    int n0 = blockIdx.x * 64, m0 = blockIdx.y * 64;
    int ty = tid / 16, tx = tid % 16;
    float acc[4][4];
    #pragma unroll
    for (int i = 0; i < 4; i++)
        #pragma unroll
        for (int j = 0; j < 4; j++) acc[i][j] = 0.f;

    for (int k0 = 0; k0 < K; k0 += 16) {
        {
            int mi = tid >> 2;      // 0..63
            int kq = tid & 3;       // 0..3
            int m = m0 + mi;
            #pragma unroll
            for (int j = 0; j < 4; j++) {
                int k = k0 + kq * 4 + j;
                As[kq * 4 + j][mi] = (m < M && k < K) ? A[m * K + k] : 0.f;
            }
        }
        {
            int kk = tid >> 6;      // 0..3
            int nn = tid & 63;
            int n = n0 + nn;
            #pragma unroll
            for (int j = 0; j < 4; j++) {
                int k = k0 + kk + j * 4;
                Wsm[kk + j * 4][nn] = (k < K && n < Nn) ? W[k * Nn + n] : 0.f;
            }
        }
        __syncthreads();
        #pragma unroll
        for (int kk = 0; kk < 16; kk++) {
            float4 a4 = *(const float4*)&As[kk][ty * 4];
            float4 b4 = *(const float4*)&Wsm[kk][tx * 4];
            acc[0][0] = fmaf(a4.x, b4.x, acc[0][0]);
            acc[0][1] = fmaf(a4.x, b4.y, acc[0][1]);
            acc[0][2] = fmaf(a4.x, b4.z, acc[0][2]);
            acc[0][3] = fmaf(a4.x, b4.w, acc[0][3]);
            acc[1][0] = fmaf(a4.y, b4.x, acc[1][0]);
            acc[1][1] = fmaf(a4.y, b4.y, acc[1][1]);
            acc[1][2] = fmaf(a4.y, b4.z, acc[1][2]);
            acc[1][3] = fmaf(a4.y, b4.w, acc[1][3]);
            acc[2][0] = fmaf(a4.z, b4.x, acc[2][0]);
            acc[2][1] = fmaf(a4.z, b4.y, acc[2][1]);
            acc[2][2] = fmaf(a4.z, b4.z, acc[2][2]);
            acc[2][3] = fmaf(a4.z, b4.w, acc[2][3]);
            acc[3][0] = fmaf(a4.w, b4.x, acc[3][0]);
            acc[3][1] = fmaf(a4.w, b4.y, acc[3][1]);
            acc[3][2] = fmaf(a4.w, b4.z, acc[3][2]);
            acc[3][3] = fmaf(a4.w, b4.w, acc[3][3]);
        }
        __syncthreads();
    }

    #pragma unroll
    for (int i = 0; i < 4; i++) {
        int m = m0 + ty * 4 + i;
        if (m >= M) continue;
        #pragma unroll
        for (int j = 0; j < 4; j++) {
            int n = n0 + tx * 4 + j;
            if (n >= Nn) continue;
            float v = acc[i][j] + bias[n];
            if (doRelu) v = fmaxf(v, 0.f);
            C[m * Nn + n] = v;
        }
    }
}

// ------------------------- final layer: sigmoid(z3 @ Wh4 + b) -> transposed out ----
__global__ void k_final(const float* __restrict__ Wh4, const float* __restrict__ bh4,
                        float* __restrict__ out) {
    __shared__ float zs[M1];
    int n = blockIdx.x;
    int tid = threadIdx.x;
    for (int k = tid; k < M1; k += 256) zs[k] = g_z3[n * M1 + k];
    __syncthreads();
    int w = tid >> 5, lane = tid & 31;
    #pragma unroll
    for (int oi = 0; oi < 3; oi++) {
        int o = w + oi * 8;
        float p = 0.f;
        for (int k = lane; k < M1; k += 32) p = fmaf(zs[k], Wh4[k * OD + o], p);
        #pragma unroll
        for (int off = 16; off; off >>= 1) p += __shfl_down_sync(0xffffffffu, p, off);
        if (lane == 0) {
            float y = fsig(p + bh4[o]);
            int b = n / LL, l = n % LL;
            out[(b * OD + o) * LL + l] = y;
        }
    }
}

// ------------------------- launcher -------------------------
extern "C" void kernel_launch(void* const* d_in, const int* in_sizes, int n_in,
                              void* d_out, int out_size) {
    const float* x    = (const float*)d_in[0];
    const float* Ahat = (const float*)d_in[1];
    const float* W1   = (const float*)d_in[2];
    const float* W2   = (const float*)d_in[3];
    const float* W_ih = (const float*)d_in[4];
    const float* W_hh = (const float*)d_in[5];
    const float* b_ih = (const float*)d_in[6];
    const float* b_hh = (const float*)d_in[7];
    const float* Wh1  = (const float*)d_in[8];
    const float* bh1  = (const float*)d_in[9];
    const float* Wh2  = (const float*)d_in[10];
    const float* bh2  = (const float*)d_in[11];
    const float* Wh3  = (const float*)d_in[12];
    const float* bh3  = (const float*)d_in[13];
    const float* Wh4  = (const float*)d_in[14];
    const float* bh4  = (const float*)d_in[15];
    float* out = (float*)d_out;

    k_prep_pn<<<1, 512>>>(W1, W2);
    k_events<<<1, 512>>>();
    k_wihT<<<(GG * H4 + 255) / 256, 256>>>(W_ih);
    k_wx<<<(HH * H4 + 255) / 256, 256>>>(W_hh, b_ih, b_hh);
    k_tables<<<(H4 + 255) / 256, 256>>>();
    k_front<<<BB * TT, 128>>>(x, Ahat);
    k_seg<<<(TT * NR + 255) / 256, 256>>>();
    k_init<<<(2 * HH * NR + 255) / 256, 256>>>();

    dim3 sgrid(16, 15);  // hcol tiles x row tiles
    for (int t = 0; t < TT; t++) {
        k_step<<<sgrid, 256>>>(t, t & 1);
    }

    k_trh<<<(NR * HH + 255) / 256, 256>>>();

    // z1 = relu(hT @ Wh1 + bh1)   [480 x 3000], K=500
    k_gemm<<<dim3((M1 + 63) / 64, (NR + 63) / 64), 256>>>(0, Wh1, bh1, 1, NR, HH, M1, 1);
    // z2 = relu(z1 @ Wh2 + bh2)   [480 x 1000], K=3000
    k_gemm<<<dim3((M2 + 63) / 64, (NR + 63) / 64), 256>>>(1, Wh2, bh2, 2, NR, M1, M2, 1);
    // z3 = relu(z2 @ Wh3 + bh3)   [480 x 3000], K=1000
    k_gemm<<<dim3((M1 + 63) / 64, (NR + 63) / 64), 256>>>(2, Wh3, bh3, 3, NR, M2, M1, 1);
    // y = sigmoid(z3 @ Wh4 + bh4) -> out[b][o][l]
    k_final<<<NR, 256>>>(Wh4, bh4, out);
}